// round 16
// baseline (speedup 1.0000x reference)
#include <cuda_runtime.h>
#include <math.h>

#define NJ     400000
#define F      128
#define TROWS  64                       // rows per tile
#define TBYTES (TROWS * F * 4)          // 32768
#define TFLOAT (TROWS * F)              // 8192
#define NTILES (NJ / TROWS)             // 6250 (exact)
#define DEPTH  3
#define NBLK   296                      // 2/SM; finalize slices: 296 = 2*148
#define TPB    256
#define WPB    (TPB / 32)               // 8 warps; 8 rows/warp/tile
#define DYN_SMEM (DEPTH * TBYTES)       // 98304

// Scratch (allocation-free rule: __device__ globals)
__device__ float g_pv[8 * F];
__device__ float g_c0;
__device__ float g_m[NBLK];
__device__ float g_s[NBLK];
__device__ float g_u[NBLK * F];
__device__ unsigned int g_cnt;

// ---------------------------------------------------------------------------
__device__ __forceinline__ unsigned smem_u32(const void* p) {
    return (unsigned)__cvta_generic_to_shared(p);
}
__device__ __forceinline__ void bulk_ld(unsigned dst, const void* src,
                                        unsigned bytes, unsigned mbar) {
    asm volatile(
        "cp.async.bulk.shared::cta.global.mbarrier::complete_tx::bytes "
        "[%0], [%1], %2, [%3];"
        :: "r"(dst), "l"(src), "r"(bytes), "r"(mbar) : "memory");
}
__device__ __forceinline__ void mbar_init(unsigned mbar, unsigned cnt) {
    asm volatile("mbarrier.init.shared.b64 [%0], %1;" :: "r"(mbar), "r"(cnt) : "memory");
}
__device__ __forceinline__ void mbar_expect_tx(unsigned mbar, unsigned bytes) {
    asm volatile("mbarrier.arrive.expect_tx.shared.b64 _, [%0], %1;"
                 :: "r"(mbar), "r"(bytes) : "memory");
}
__device__ __forceinline__ void mbar_wait(unsigned mbar, unsigned parity) {
    asm volatile(
        "{\n\t.reg .pred P;\n\t"
        "W_%=:\n\t"
        "mbarrier.try_wait.parity.acquire.cta.shared::cta.b64 P, [%0], %1, 0x989680;\n\t"
        "@P bra D_%=;\n\t"
        "bra W_%=;\n\t"
        "D_%=:\n\t}"
        :: "r"(mbar), "r"(parity) : "memory");
}

// ---------------------------------------------------------------------------
// Kernel A: precompute, grid = 9 blocks x 1024 threads (proven ~3us).
// ---------------------------------------------------------------------------
__global__ void __launch_bounds__(1024) prep_kernel(
        const float* __restrict__ h_i,
        const float* __restrict__ W_i_w,
        const float* __restrict__ W_i_b,
        const float* __restrict__ W_j_w,
        const float* __restrict__ W_j_b,
        const float* __restrict__ W_ij) {
    const int tid  = threadIdx.x;
    const int b    = blockIdx.x;

    if (b < 8) {
        __shared__ float s_p[8 * F];
        const int t   = tid & 127;
        const int sub = tid >> 7;
        const int f0  = b * 16 + sub * 2;
        float acc = W_j_w[f0 * F + t]       * W_ij[F + f0]
                  + W_j_w[(f0 + 1) * F + t] * W_ij[F + f0 + 1];
        s_p[sub * F + t] = acc;
        __syncthreads();
        if (tid < F) {
            float v = 0.f;
#pragma unroll
            for (int s = 0; s < 8; s++) v += s_p[s * F + tid];
            g_pv[b * F + tid] = v;
        }
        return;
    }

    __shared__ __align__(16) float s_hi[F];
    __shared__ float s_z[F];
    __shared__ float s_red[F];
    const int wid  = tid >> 5;
    const int lane = tid & 31;

    if (tid == 0) g_cnt = 0u;
    if (tid < F) s_hi[tid] = h_i[tid];
    __syncthreads();

    const float4 hv = reinterpret_cast<const float4*>(s_hi)[lane];
    const float4 w0 = reinterpret_cast<const float4*>(W_i_w + (wid      ) * F)[lane];
    const float4 w1 = reinterpret_cast<const float4*>(W_i_w + (wid + 32 ) * F)[lane];
    const float4 w2 = reinterpret_cast<const float4*>(W_i_w + (wid + 64 ) * F)[lane];
    const float4 w3 = reinterpret_cast<const float4*>(W_i_w + (wid + 96 ) * F)[lane];
    float d0 = w0.x*hv.x + w0.y*hv.y + w0.z*hv.z + w0.w*hv.w;
    float d1 = w1.x*hv.x + w1.y*hv.y + w1.z*hv.z + w1.w*hv.w;
    float d2 = w2.x*hv.x + w2.y*hv.y + w2.z*hv.z + w2.w*hv.w;
    float d3 = w3.x*hv.x + w3.y*hv.y + w3.z*hv.z + w3.w*hv.w;
#pragma unroll
    for (int off = 16; off > 0; off >>= 1) {
        d0 += __shfl_xor_sync(0xffffffffu, d0, off);
        d1 += __shfl_xor_sync(0xffffffffu, d1, off);
        d2 += __shfl_xor_sync(0xffffffffu, d2, off);
        d3 += __shfl_xor_sync(0xffffffffu, d3, off);
    }
    if (lane == 0) {
        s_z[wid     ] = d0 + W_i_b[wid     ];
        s_z[wid + 32] = d1 + W_i_b[wid + 32];
        s_z[wid + 64] = d2 + W_i_b[wid + 64];
        s_z[wid + 96] = d3 + W_i_b[wid + 96];
    }
    __syncthreads();

    if (tid < F) s_red[tid] = W_ij[tid] * s_z[tid] + W_j_b[tid] * W_ij[F + tid];
    __syncthreads();
    if (tid < 64) s_red[tid] += s_red[tid + 64];
    __syncthreads();
    if (tid < 32) {
        float c = s_red[tid] + s_red[tid + 32];
#pragma unroll
        for (int off = 16; off > 0; off >>= 1)
            c += __shfl_xor_sync(0xffffffffu, c, off);
        if (tid == 0) g_c0 = c;
    }
}

// ---------------------------------------------------------------------------
// Kernel B: bulk-async (TMA-path) staged pipeline.
// Ring of DEPTH 64-row tiles in dynamic smem, filled by tid0 via
// cp.async.bulk + mbarrier. 8 warps x 8 rows/tile, R13 math from LDS.
// ---------------------------------------------------------------------------
__global__ void __launch_bounds__(TPB, 2) pass_kernel(
        const float* __restrict__ h_j,
        const float* __restrict__ W_j_w,
        const float* __restrict__ W_j_b,
        float* __restrict__ out) {
    extern __shared__ __align__(16) float tiles[];   // [DEPTH][TFLOAT]
    __shared__ __align__(8) unsigned long long mbar[DEPTH];
    __shared__ __align__(16) float sv[F];
    __shared__ float red_m[WPB];
    __shared__ float red_s[WPB];
    __shared__ float red_u[WPB * F];
    __shared__ float s_mb;

    const int tid  = threadIdx.x;
    const int warp = tid >> 5;
    const int lane = tid & 31;

    if (tid < F) {
        float v = 0.f;
#pragma unroll
        for (int s = 0; s < 8; s++) v += g_pv[s * F + tid];
        sv[tid] = v;
    }
    if (tid == 0) {
#pragma unroll
        for (int s = 0; s < DEPTH; s++) mbar_init(smem_u32(&mbar[s]), 1);
    }
    __syncthreads();

    // prime DEPTH tiles
    if (tid == 0) {
#pragma unroll
        for (int k = 0; k < DEPTH; k++) {
            const int t = blockIdx.x + k * NBLK;
            if (t < NTILES) {
                mbar_expect_tx(smem_u32(&mbar[k]), TBYTES);
                bulk_ld(smem_u32(tiles + k * TFLOAT),
                        h_j + (size_t)t * TFLOAT, TBYTES,
                        smem_u32(&mbar[k]));
            }
        }
    }

    const float c0 = g_c0;
    const float4 vv = reinterpret_cast<const float4*>(sv)[lane];

    float m = -1e30f, ssum = 0.f;
    float ux = 0.f, uy = 0.f, uz = 0.f, uw = 0.f;

    int i = 0;
    for (int t = blockIdx.x; t < NTILES; t += NBLK, ++i) {
        const int s  = i % DEPTH;
        const int ph = (i / DEPTH) & 1;
        mbar_wait(smem_u32(&mbar[s]), (unsigned)ph);

        const float4* tile4 = reinterpret_cast<const float4*>(tiles + s * TFLOAT);

        // 8 rows for this warp, from smem (conflict-free LDS.128)
        float4 xa[8];
#pragma unroll
        for (int r = 0; r < 8; r++)
            xa[r] = tile4[(warp * 8 + r) * 32 + lane];

        float d[8];
#pragma unroll
        for (int r = 0; r < 8; r++)
            d[r] = xa[r].x*vv.x + xa[r].y*vv.y + xa[r].z*vv.z + xa[r].w*vv.w;
#pragma unroll
        for (int off = 16; off > 0; off >>= 1) {
#pragma unroll
            for (int r = 0; r < 8; r++)
                d[r] += __shfl_xor_sync(0xffffffffu, d[r], off);
        }

        float e[8];
#pragma unroll
        for (int r = 0; r < 8; r++) {
            const float sc = d[r] + c0;
            e[r] = (sc > 0.f) ? sc : 0.1f * sc;
        }

        float mn = m;
#pragma unroll
        for (int r = 0; r < 8; r++) mn = fmaxf(mn, e[r]);
        const float scale = __expf(m - mn);
        float w[8], wsum = 0.f;
#pragma unroll
        for (int r = 0; r < 8; r++) { w[r] = __expf(e[r] - mn); wsum += w[r]; }
        ssum = ssum * scale + wsum;
        float ax = 0.f, ay = 0.f, az = 0.f, aw = 0.f;
#pragma unroll
        for (int r = 0; r < 8; r++) {
            ax += w[r] * xa[r].x;
            ay += w[r] * xa[r].y;
            az += w[r] * xa[r].z;
            aw += w[r] * xa[r].w;
        }
        ux = ux * scale + ax;
        uy = uy * scale + ay;
        uz = uz * scale + az;
        uw = uw * scale + aw;
        m = mn;

        __syncthreads();   // all warps done reading slot s

        if (tid == 0) {
            const int nt = t + DEPTH * NBLK;
            if (nt < NTILES) {
                asm volatile("fence.proxy.async.shared::cta;" ::: "memory");
                mbar_expect_tx(smem_u32(&mbar[s]), TBYTES);
                bulk_ld(smem_u32(tiles + s * TFLOAT),
                        h_j + (size_t)nt * TFLOAT, TBYTES,
                        smem_u32(&mbar[s]));
            }
        }
    }

    // ---- block combine (8 warps) ----
    if (lane == 0) { red_m[warp] = m; red_s[warp] = ssum; }
    red_u[warp * F + lane * 4 + 0] = ux;
    red_u[warp * F + lane * 4 + 1] = uy;
    red_u[warp * F + lane * 4 + 2] = uz;
    red_u[warp * F + lane * 4 + 3] = uw;
    __syncthreads();

    if (tid == 0) {
        float mb = red_m[0];
#pragma unroll
        for (int w2 = 1; w2 < WPB; w2++) mb = fmaxf(mb, red_m[w2]);
        s_mb = mb;
    }
    __syncthreads();
    const float mb = s_mb;

    if (tid < F) {
        float acc = 0.f;
#pragma unroll
        for (int w2 = 0; w2 < WPB; w2++)
            acc += __expf(red_m[w2] - mb) * red_u[w2 * F + tid];
        g_u[blockIdx.x * F + tid] = acc;
    }
    if (tid == 0) {
        float sb = 0.f;
#pragma unroll
        for (int w2 = 0; w2 < WPB; w2++) sb += __expf(red_m[w2] - mb) * red_s[w2];
        g_s[blockIdx.x] = sb;
        g_m[blockIdx.x] = mb;
    }
    __syncthreads();

    // ---- last-block fused finalize ----
    __shared__ unsigned int s_last;
    __threadfence();
    if (tid == 0)
        s_last = (atomicAdd(&g_cnt, 1u) == (unsigned)(NBLK - 1)) ? 1u : 0u;
    __syncthreads();
    if (!s_last) return;

    __shared__ float sf[NBLK];
    __shared__ float s_pu[2 * F];
    __shared__ __align__(16) float sun[F];
    __shared__ float s_r[WPB];
    __shared__ float s_mg, s_S;

    const int t = tid;
    {
        float lm = -1e30f;
        for (int b = t; b < NBLK; b += TPB) lm = fmaxf(lm, g_m[b]);
#pragma unroll
        for (int off = 16; off > 0; off >>= 1)
            lm = fmaxf(lm, __shfl_xor_sync(0xffffffffu, lm, off));
        if (lane == 0) s_r[warp] = lm;
        __syncthreads();
        if (t == 0) {
            float v = s_r[0];
#pragma unroll
            for (int w2 = 1; w2 < WPB; w2++) v = fmaxf(v, s_r[w2]);
            s_mg = v;
        }
        __syncthreads();
    }
    const float mg = s_mg;

    {
        float ls = 0.f;
        for (int b = t; b < NBLK; b += TPB) {
            const float fct = __expf(g_m[b] - mg);
            sf[b] = fct;
            ls += fct * g_s[b];
        }
#pragma unroll
        for (int off = 16; off > 0; off >>= 1)
            ls += __shfl_xor_sync(0xffffffffu, ls, off);
        if (lane == 0) s_r[warp] = ls;
        __syncthreads();
        if (t == 0) {
            float v = 0.f;
#pragma unroll
            for (int w2 = 0; w2 < WPB; w2++) v += s_r[w2];
            s_S = v;
        }
        __syncthreads();
    }
    const float S = s_S;

    {
        const int slice = t >> 7;
        const int tf    = t & 127;
        const int b0    = slice * 148;
        float acc = 0.f;
#pragma unroll 4
        for (int k = 0; k < 148; k++)
            acc += sf[b0 + k] * g_u[(b0 + k) * F + tf];
        s_pu[slice * F + tf] = acc;
    }
    __syncthreads();
    if (t < F) sun[t] = (s_pu[t] + s_pu[F + t]) / S;
    __syncthreads();

    const float4 uv = reinterpret_cast<const float4*>(sun)[lane];
#pragma unroll 4
    for (int r = 0; r < 16; r++) {
        const int f = warp + WPB * r;
        const float4 wrow = reinterpret_cast<const float4*>(W_j_w + f * F)[lane];
        float d = wrow.x*uv.x + wrow.y*uv.y + wrow.z*uv.z + wrow.w*uv.w;
#pragma unroll
        for (int off = 16; off > 0; off >>= 1)
            d += __shfl_xor_sync(0xffffffffu, d, off);
        if (lane == 0) {
            const float h = d + W_j_b[f];
            out[f] = (h > 0.f) ? h : expm1f(h);
        }
    }
}

// ---------------------------------------------------------------------------
extern "C" void kernel_launch(void* const* d_in, const int* in_sizes, int n_in,
                              void* d_out, int out_size) {
    const float* h_i   = (const float*)d_in[0];
    const float* h_j   = (const float*)d_in[1];
    const float* W_i_w = (const float*)d_in[2];
    const float* W_i_b = (const float*)d_in[3];
    const float* W_j_w = (const float*)d_in[4];
    const float* W_j_b = (const float*)d_in[5];
    const float* W_ij  = (const float*)d_in[6];
    float* out = (float*)d_out;

    cudaFuncSetAttribute(pass_kernel,
                         cudaFuncAttributeMaxDynamicSharedMemorySize, DYN_SMEM);

    prep_kernel<<<9, 1024>>>(h_i, W_i_w, W_i_b, W_j_w, W_j_b, W_ij);
    pass_kernel<<<NBLK, TPB, DYN_SMEM>>>(h_j, W_j_w, W_j_b, out);
}